// round 2
// baseline (speedup 1.0000x reference)
#include <cuda_runtime.h>

#define NN      50000
#define DIM     512
#define KMAX    32
#define NTHREADS 256
#define NWARPS  (NTHREADS / 32)

// Per-node completion flags (zero-initialized at load; reset each launch).
__device__ volatile int g_done[NN];

__global__ void reset_kernel() {
    int i = blockIdx.x * blockDim.x + threadIdx.x;
    if (i < NN) g_done[i] = 0;
}

__global__ void __launch_bounds__(NTHREADS, 3)
attn_kernel(const float* __restrict__ feats,
            const float* __restrict__ wq_w,
            const float* __restrict__ wq_b,
            const float* __restrict__ wk_w,
            const float* __restrict__ wk_b,
            const int*   __restrict__ neighbors,
            const int*   __restrict__ deg,
            float*       out)
{
    extern __shared__ float s_rows[];          // KMAX * DIM floats = 64 KB
    __shared__ int   s_nbr[KMAX];
    __shared__ float s_ej[KMAX];
    __shared__ float s_a[KMAX];
    __shared__ float s_red[NWARPS];
    __shared__ float s_ei;

    const int i    = blockIdx.x;
    const int tid  = threadIdx.x;
    const int lane = tid & 31;
    const int warp = tid >> 5;
    const int d    = deg[i];                   // uniform across block

    // ---- Wait for earlier-indexed valid neighbors to be done (acquire) ----
    if (tid < KMAX) {
        int nb = neighbors[i * KMAX + tid];
        s_nbr[tid] = nb;
        if (tid < d && nb < i) {
            while (g_done[nb] == 0) { __nanosleep(64); }
            __threadfence();                   // acquire: order flag before row reads
        }
    }
    __syncthreads();

    // ---- ei partial: dot(feats[i], wq_w) ----
    const float* fi = feats + (size_t)i * DIM;
    {
        float p = 0.f;
        #pragma unroll 2
        for (int j = tid; j < DIM; j += NTHREADS) p += fi[j] * wq_w[j];
        #pragma unroll
        for (int o = 16; o > 0; o >>= 1) p += __shfl_down_sync(0xffffffffu, p, o);
        if (lane == 0) s_red[warp] = p;
    }

    // ---- Gather valid neighbor rows into smem (updated for nb<i, else orig) ----
    for (int k = warp; k < d; k += NWARPS) {
        int nb = s_nbr[k];
        const float4* src = (const float4*)((nb < i ? out : feats) + (size_t)nb * DIM);
        float4* dst = (float4*)(s_rows + k * DIM);
        #pragma unroll
        for (int j = lane; j < DIM / 4; j += 32) dst[j] = src[j];
    }
    __syncthreads();

    // ---- finalize ei; ej_k = dot(row_k, wk_w) + wk_b ----
    if (tid == 0) {
        float e = 0.f;
        #pragma unroll
        for (int w = 0; w < NWARPS; w++) e += s_red[w];
        s_ei = e + wq_b[0];
    }
    const float wkb = wk_b[0];
    for (int k = warp; k < d; k += NWARPS) {
        const float* row = s_rows + k * DIM;
        float p = 0.f;
        #pragma unroll 4
        for (int j = lane; j < DIM; j += 32) p += row[j] * wk_w[j];
        #pragma unroll
        for (int o = 16; o > 0; o >>= 1) p += __shfl_down_sync(0xffffffffu, p, o);
        if (lane == 0) s_ej[k] = p + wkb;
    }
    __syncthreads();

    // ---- masked softmax over the d valid scores (warp 0) ----
    if (warp == 0) {
        const float NEG = -3.4e38f;
        float e = (lane < d) ? s_ei * s_ej[lane] : NEG;
        float m = e;
        #pragma unroll
        for (int o = 16; o > 0; o >>= 1) m = fmaxf(m, __shfl_xor_sync(0xffffffffu, m, o));
        float ex = (lane < d) ? expf(e - m) : 0.f;
        float s = ex;
        #pragma unroll
        for (int o = 16; o > 0; o >>= 1) s += __shfl_xor_sync(0xffffffffu, s, o);
        if (lane < d) s_a[lane] = ex / s;
    }
    __syncthreads();

    // ---- out[i] = feats[i] + sum_k a_k * row_k ----
    float* oi = out + (size_t)i * DIM;
    #pragma unroll 2
    for (int j = tid; j < DIM; j += NTHREADS) {
        float acc = fi[j];
        #pragma unroll 8
        for (int k = 0; k < d; k++) acc = fmaf(s_a[k], s_rows[k * DIM + j], acc);
        oi[j] = acc;
    }
    __syncthreads();

    // ---- release: publish this row ----
    if (tid == 0) {
        __threadfence();
        g_done[i] = 1;
    }
}

extern "C" void kernel_launch(void* const* d_in, const int* in_sizes, int n_in,
                              void* d_out, int out_size) {
    const float* feats     = (const float*)d_in[0];
    const float* wq_w      = (const float*)d_in[1];
    const float* wq_b      = (const float*)d_in[2];
    const float* wk_w      = (const float*)d_in[3];
    const float* wk_b      = (const float*)d_in[4];
    const int*   neighbors = (const int*)d_in[5];
    const int*   deg       = (const int*)d_in[6];
    float*       out       = (float*)d_out;

    static bool attr_set = false;
    if (!attr_set) {
        cudaFuncSetAttribute(attn_kernel,
                             cudaFuncAttributeMaxDynamicSharedMemorySize,
                             KMAX * DIM * (int)sizeof(float));
        attr_set = true;
    }

    reset_kernel<<<(NN + 255) / 256, 256>>>();
    attn_kernel<<<NN, NTHREADS, KMAX * DIM * sizeof(float)>>>(
        feats, wq_w, wq_b, wk_w, wk_b, neighbors, deg, out);
}